// round 16
// baseline (speedup 1.0000x reference)
#include <cuda_runtime.h>
#include <math.h>

#define TT 2048
#define HH 8
#define DD 128
#define MM 4096
#define LL 512
#define RC 32                     // row chunks for attn column-sum
#define ROWS_PER_CHUNK (TT / RC)  // 64

// block-range partition of the fused main kernel
#define NB_ATTN 256               // one block per (h, rc); 2 float4 cols/thread
#define NB_EMB  TT                // one block per t
#define NB_KVQ  (HH * TT / 8)     // 8 warps per block, one warp per (h,t)
#define NB_MAIN (NB_ATTN + NB_EMB + NB_KVQ)

// ---------------- device scratch (no allocations allowed) ----------------
__device__ float    g_part[HH * RC * TT];   // attn partial column sums (2 MB)
__device__ float    g_knorm[HH * TT];
__device__ float    g_vnorm[HH * TT];
__device__ float    g_qnorm[HH * TT];
__device__ float    g_enorm[TT];
__device__ unsigned g_prio_u[HH * TT];      // order-mapped priority bits
__device__ int      g_keep[HH * LL];

// ---------------- 1) fused: attn partials + emb norm + kvq norms ----------------
// attn: one block per (h, rc), each thread owns 2 float4 columns -> 2
// independent loads per row step (deeper MLP). Per-column FP summation order
// is IDENTICAL to the measured-correct version (bit-identical priorities).
// attn/x/q are read-once -> __ldcs evict-first keeps k/v L2-resident.
__global__ void main_fused_kernel(const float* __restrict__ attn,
                                  const float* __restrict__ k,
                                  const float* __restrict__ v,
                                  const float* __restrict__ q,
                                  const float* __restrict__ x) {
    int b = blockIdx.x;
    if (b < NB_ATTN) {
        // ---- attn weighted column partial sums (2 float4 cols / thread) ----
        int h  = b >> 5;           // 32 blocks per head
        int rc = b & 31;
        int c4a = threadIdx.x;             // float4 column 0..255
        int c4b = threadIdx.x + 256;       // float4 column 256..511
        int row0 = rc * ROWS_PER_CHUNK;
        const float4* base = (const float4*)attn + ((size_t)(h * TT + row0) * TT >> 2);
        float4 sa = make_float4(0.f, 0.f, 0.f, 0.f);
        float4 sb = make_float4(0.f, 0.f, 0.f, 0.f);
#pragma unroll 8
        for (int i = 0; i < ROWS_PER_CHUNK; ++i) {
            const float4* rowp = base + (size_t)i * (TT / 4);
            float4 a0 = __ldcs(rowp + c4a);
            float4 a1 = __ldcs(rowp + c4b);
            float w = (float)(row0 + i + 1);
            sa.x += a0.x * w; sa.y += a0.y * w; sa.z += a0.z * w; sa.w += a0.w * w;
            sb.x += a1.x * w; sb.y += a1.y * w; sb.z += a1.z * w; sb.w += a1.w * w;
        }
        float4* op = (float4*)&g_part[(h * RC + rc) * TT];
        op[c4a] = sa;
        op[c4b] = sb;
    } else if (b < NB_ATTN + NB_EMB) {
        // ---- emb norm: one block per t over 4096 floats ----
        int t = b - NB_ATTN;
        const float4* xp = (const float4*)(x + (size_t)t * MM);
        float s = 0.0f;
        for (int i = threadIdx.x; i < MM / 4; i += 256) {
            float4 u = __ldcs(&xp[i]);
            s += u.x * u.x + u.y * u.y + u.z * u.z + u.w * u.w;
        }
#pragma unroll
        for (int o = 16; o > 0; o >>= 1) s += __shfl_xor_sync(0xffffffffu, s, o);
        __shared__ float red[8];
        int lane = threadIdx.x & 31, w = threadIdx.x >> 5;
        if (lane == 0) red[w] = s;
        __syncthreads();
        if (threadIdx.x == 0) {
            float tot = 0.0f;
#pragma unroll
            for (int i = 0; i < 8; ++i) tot += red[i];
            g_enorm[t] = sqrtf(tot);
        }
    } else {
        // ---- kvq norms: one warp per (h,t) ----
        int warp = (b - NB_ATTN - NB_EMB) * 8 + (threadIdx.x >> 5);
        int lane = threadIdx.x & 31;
        int h = warp >> 11;
        int t = warp & (TT - 1);

        const float4* kp = (const float4*)(k + ((size_t)(h * TT + t)) * DD);
        float4 a = kp[lane];
        float ks = a.x * a.x + a.y * a.y + a.z * a.z + a.w * a.w;

        const float4* vp = (const float4*)(v + ((size_t)(h * TT + t)) * DD);
        float4 bb = vp[lane];
        float vs = bb.x * bb.x + bb.y * bb.y + bb.z * bb.z + bb.w * bb.w;

        float4 acc = make_float4(0.f, 0.f, 0.f, 0.f);
#pragma unroll
        for (int g = 0; g < 4; ++g) {
            const float4* qp = (const float4*)(q + ((size_t)((h * 4 + g) * TT + t)) * DD);
            float4 u = __ldcs(&qp[lane]);
            acc.x += u.x; acc.y += u.y; acc.z += u.z; acc.w += u.w;
        }
        acc.x *= 0.25f; acc.y *= 0.25f; acc.z *= 0.25f; acc.w *= 0.25f;
        float qs = acc.x * acc.x + acc.y * acc.y + acc.z * acc.z + acc.w * acc.w;

#pragma unroll
        for (int o = 16; o > 0; o >>= 1) {
            ks += __shfl_xor_sync(0xffffffffu, ks, o);
            vs += __shfl_xor_sync(0xffffffffu, vs, o);
            qs += __shfl_xor_sync(0xffffffffu, qs, o);
        }
        if (lane == 0) {
            g_knorm[warp] = sqrtf(ks);
            g_vnorm[warp] = sqrtf(vs);
            g_qnorm[warp] = sqrtf(qs);
        }
    }
}

// ---------------- 2) wide priority: partial reduce + MLP, one thread per (h,t) ----------------
// 128 blocks x 128 threads; 16 blocks per head so weights are uniform per block.
__global__ void prio_kernel(const float* __restrict__ W1, const float* __restrict__ b1,
                            const float* __restrict__ W2, const float* __restrict__ b2) {
    int idx = blockIdx.x * 128 + threadIdx.x;  // 0..16383
    int h = idx >> 11;
    int t = idx & (TT - 1);

    __shared__ float sW1[50], sb1[10], sW2[10], sb2;
    if (threadIdx.x < 50) sW1[threadIdx.x] = W1[h * 50 + threadIdx.x];
    if (threadIdx.x >= 64 && threadIdx.x < 74) {
        sb1[threadIdx.x - 64] = b1[h * 10 + threadIdx.x - 64];
        sW2[threadIdx.x - 64] = W2[h * 10 + threadIdx.x - 64];
    }
    if (threadIdx.x == 96) sb2 = b2[h];
    __syncthreads();

    float s = 0.0f;
#pragma unroll
    for (int rc = 0; rc < RC; ++rc) s += g_part[(h * RC + rc) * TT + t];
    float f0 = s / (float)(TT - t);
    float f1 = g_knorm[idx];
    float f2 = g_vnorm[idx];
    float f3 = g_qnorm[idx];
    float f4 = g_enorm[t];

    float p = sb2;
#pragma unroll
    for (int kk = 0; kk < 10; ++kk) {
        float hs = sb1[kk];
        hs += f0 * sW1[kk];
        hs += f1 * sW1[10 + kk];
        hs += f2 * sW1[20 + kk];
        hs += f3 * sW1[30 + kk];
        hs += f4 * sW1[40 + kk];
        p += fmaxf(hs, 0.0f) * sW2[kk];
    }
    unsigned u = __float_as_uint(p);
    u = (u & 0x80000000u) ? ~u : (u | 0x80000000u);  // monotone order map
    g_prio_u[idx] = u;
}

// ---------------- 3) radix-select top-512 per head ----------------
// One block per head, 1024 threads. Exact top-512 by value, ties -> lower
// index (matches lax.top_k), indices ascending via stable t-order compaction.
__global__ void __launch_bounds__(1024, 1)
topk_kernel(float* __restrict__ out_idx_as_float) {
    int h = blockIdx.x;
    int tid = threadIdx.x;
    int lane = tid & 31, wid = tid >> 5;

    __shared__ unsigned su[TT];
    __shared__ unsigned hist[256];
    __shared__ unsigned wsum[32];
    __shared__ unsigned s_prefix;
    __shared__ int      s_rem;

    if (tid == 0) { s_prefix = 0u; s_rem = LL; }
    su[tid] = g_prio_u[h * TT + tid];
    su[tid + 1024] = g_prio_u[h * TT + tid + 1024];
    __syncthreads();

    // ---- 4-pass radix select of the 512th largest value (exact bits) ----
    for (int pass = 0; pass < 4; ++pass) {
        int shift = 24 - 8 * pass;
        if (tid < 256) hist[tid] = 0u;
        __syncthreads();
        unsigned pref = s_prefix;
#pragma unroll
        for (int t = tid; t < TT; t += 1024) {
            unsigned u = su[t];
            bool cand = (pass == 0) || ((u >> (shift + 8)) == (pref >> (shift + 8)));
            if (cand) atomicAdd(&hist[(u >> shift) & 255u], 1u);
        }
        __syncthreads();
        if (tid < 32) {
            int rem = s_rem;
            unsigned pfx = s_prefix;
            __syncwarp();
            unsigned local[8];
            unsigned lsum = 0;
#pragma unroll
            for (int i = 0; i < 8; ++i) { local[i] = hist[255 - (tid * 8 + i)]; lsum += local[i]; }
            unsigned inc = lsum;
#pragma unroll
            for (int o = 1; o < 32; o <<= 1) {
                unsigned n = __shfl_up_sync(0xffffffffu, inc, o);
                if (lane >= o) inc += n;
            }
            unsigned cum = inc - lsum;   // count in bins strictly above my group
#pragma unroll
            for (int i = 0; i < 8; ++i) {
                unsigned above = cum;
                cum += local[i];
                int bin = 255 - (tid * 8 + i);
                if (above < (unsigned)rem && cum >= (unsigned)rem) {
                    s_prefix = pfx | ((unsigned)bin << shift);
                    s_rem = rem - (int)above;
                }
            }
        }
        __syncthreads();
    }

    unsigned thr = s_prefix;           // exact bits of the 512th largest
    unsigned extra = (unsigned)s_rem;  // # of (== thr) elements to keep (lowest t first)

    // ---- stable compaction: selected = (u > thr) || (u == thr && eq_rank < extra)
    int t0 = 2 * tid, t1 = 2 * tid + 1;
    unsigned u0 = su[t0], u1 = su[t1];
    unsigned gt0 = (u0 > thr), eq0 = (u0 == thr);
    unsigned gt1 = (u1 > thr), eq1 = (u1 == thr);
    unsigned cnt = (gt0 + gt1) | ((eq0 + eq1) << 16);

    unsigned inc = cnt;
#pragma unroll
    for (int o = 1; o < 32; o <<= 1) {
        unsigned n = __shfl_up_sync(0xffffffffu, inc, o);
        if (lane >= o) inc += n;
    }
    if (lane == 31) wsum[wid] = inc;
    __syncthreads();
    if (tid < 32) {
        unsigned a = wsum[tid];
        unsigned in2 = a;
#pragma unroll
        for (int o = 1; o < 32; o <<= 1) {
            unsigned n = __shfl_up_sync(0xffffffffu, in2, o);
            if (lane >= o) in2 += n;
        }
        wsum[tid] = in2 - a;   // exclusive warp offsets
    }
    __syncthreads();
    unsigned excl = wsum[wid] + inc - cnt;     // packed exclusive prefix
    unsigned gt_b = excl & 0xffffu;
    unsigned eq_b = excl >> 16;

    if (gt0 || (eq0 && eq_b < extra)) {
        unsigned pos = gt_b + min(eq_b, extra);
        g_keep[h * LL + pos] = t0;
        out_idx_as_float[h * LL + pos] = (float)t0;
    }
    gt_b += gt0; eq_b += eq0;
    if (gt1 || (eq1 && eq_b < extra)) {
        unsigned pos = gt_b + min(eq_b, extra);
        g_keep[h * LL + pos] = t1;
        out_idx_as_float[h * LL + pos] = (float)t1;
    }
}

// ---------------- 4) gather: one warp per 2 rows, k+v both -> MLP=4 (best measured) ----------------
// 256 blocks x 256 threads = 2048 warps for 4096 rows.
__global__ void gather_kernel(const float* __restrict__ k,
                              const float* __restrict__ v,
                              float* __restrict__ out) {
    int widg = (blockIdx.x * blockDim.x + threadIdx.x) >> 5;  // 0..2047
    int lane = threadIdx.x & 31;
    int r0 = widg * 2;                 // rows r0, r0+1 (global row = h*512 + l)
    int h0 = r0 >> 9;
    int h1 = (r0 + 1) >> 9;

    // broadcast index loads (independent -> both in flight)
    int t0 = g_keep[r0];
    int t1 = g_keep[r0 + 1];

    // 4 independent 512B row reads in flight per warp (L2-hot after main)
    float4 k0 = ((const float4*)(k + ((size_t)(h0 * TT + t0)) * DD))[lane];
    float4 v0 = ((const float4*)(v + ((size_t)(h0 * TT + t0)) * DD))[lane];
    float4 k1 = ((const float4*)(k + ((size_t)(h1 * TT + t1)) * DD))[lane];
    float4 v1 = ((const float4*)(v + ((size_t)(h1 * TT + t1)) * DD))[lane];

    float* ko = out + (size_t)HH * LL;
    float* vo = ko + (size_t)HH * LL * DD;
    ((float4*)(ko + (size_t)r0 * DD))[lane] = k0;
    ((float4*)(vo + (size_t)r0 * DD))[lane] = v0;
    ((float4*)(ko + (size_t)(r0 + 1) * DD))[lane] = k1;
    ((float4*)(vo + (size_t)(r0 + 1) * DD))[lane] = v1;
}

// ---------------- launch ----------------
extern "C" void kernel_launch(void* const* d_in, const int* in_sizes, int n_in,
                              void* d_out, int out_size) {
    // metadata order: input_pos, k_val, v_val, query, x, attn, W1, b1, W2, b2
    const float* k    = (const float*)d_in[1];
    const float* v    = (const float*)d_in[2];
    const float* q    = (const float*)d_in[3];
    const float* x    = (const float*)d_in[4];
    const float* attn = (const float*)d_in[5];
    const float* W1   = (const float*)d_in[6];
    const float* b1   = (const float*)d_in[7];
    const float* W2   = (const float*)d_in[8];
    const float* b2   = (const float*)d_in[9];
    float* out = (float*)d_out;  // [keep_idxs(4096) | k_out(524288) | v_out(524288)]

    main_fused_kernel<<<NB_MAIN, 256>>>(attn, k, v, q, x);
    prio_kernel<<<HH * TT / 128, 128>>>(W1, b1, W2, b2);
    topk_kernel<<<HH, 1024>>>(out);
    gather_kernel<<<HH * LL / 16, 256>>>(k, v, out);
}

// round 17
// speedup vs baseline: 1.1489x; 1.1489x over previous
#include <cuda_runtime.h>
#include <math.h>

#define TT 2048
#define HH 8
#define DD 128
#define MM 4096
#define LL 512
#define RC 32                     // row chunks for attn column-sum
#define ROWS_PER_CHUNK (TT / RC)  // 64

// block-range partition of the fused main kernel
#define NB_ATTN 512               // (TT/4/256=2) * RC * HH
#define NB_EMB  TT                // one block per t
#define NB_KVQ  (HH * TT / 8)     // 8 warps per block, one warp per (h,t)
#define NB_MAIN (NB_ATTN + NB_EMB + NB_KVQ)

// ---------------- device scratch (no allocations allowed) ----------------
__device__ float    g_part[HH * RC * TT];   // attn partial column sums (2 MB)
__device__ float    g_knorm[HH * TT];
__device__ float    g_vnorm[HH * TT];
__device__ float    g_qnorm[HH * TT];
__device__ float    g_enorm[TT];
__device__ unsigned g_prio_u[HH * TT];      // order-mapped priority bits
__device__ int      g_keep[HH * LL];

// ---------------- 1) fused: attn partials + emb norm + kvq norms ----------------
// (measured-best configuration: 35.5us @ 76.9% DRAM / 6.29 TB/s. The 1-col/
//  thread, 512-attn-CTA shape interleaves with the emb/kvq latency blocks —
//  every perturbation of this kernel measured slower. attn/x/q read-once via
//  __ldcs evict-first keeps k/v L2-resident for the gather.)
__global__ void main_fused_kernel(const float* __restrict__ attn,
                                  const float* __restrict__ k,
                                  const float* __restrict__ v,
                                  const float* __restrict__ q,
                                  const float* __restrict__ x) {
    int b = blockIdx.x;
    if (b < NB_ATTN) {
        // ---- attn weighted column partial sums (float4, 4 cols/thread) ----
        int h  = b >> 6;           // 64 blocks per head
        int rc = (b >> 1) & 31;
        int c4 = (b & 1) * 256 + threadIdx.x;   // float4 column index 0..511
        int row0 = rc * ROWS_PER_CHUNK;
        const float4* base = (const float4*)attn + ((size_t)(h * TT + row0) * TT >> 2) + c4;
        float4 s = make_float4(0.f, 0.f, 0.f, 0.f);
#pragma unroll 16
        for (int i = 0; i < ROWS_PER_CHUNK; ++i) {
            float4 a = __ldcs(&base[(size_t)i * (TT / 4)]);
            float w = (float)(row0 + i + 1);
            s.x += a.x * w; s.y += a.y * w; s.z += a.z * w; s.w += a.w * w;
        }
        ((float4*)&g_part[(h * RC + rc) * TT])[c4] = s;
    } else if (b < NB_ATTN + NB_EMB) {
        // ---- emb norm: one block per t over 4096 floats ----
        int t = b - NB_ATTN;
        const float4* xp = (const float4*)(x + (size_t)t * MM);
        float s = 0.0f;
        for (int i = threadIdx.x; i < MM / 4; i += 256) {
            float4 u = __ldcs(&xp[i]);
            s += u.x * u.x + u.y * u.y + u.z * u.z + u.w * u.w;
        }
#pragma unroll
        for (int o = 16; o > 0; o >>= 1) s += __shfl_xor_sync(0xffffffffu, s, o);
        __shared__ float red[8];
        int lane = threadIdx.x & 31, w = threadIdx.x >> 5;
        if (lane == 0) red[w] = s;
        __syncthreads();
        if (threadIdx.x == 0) {
            float tot = 0.0f;
#pragma unroll
            for (int i = 0; i < 8; ++i) tot += red[i];
            g_enorm[t] = sqrtf(tot);
        }
    } else {
        // ---- kvq norms: one warp per (h,t) ----
        int warp = (b - NB_ATTN - NB_EMB) * 8 + (threadIdx.x >> 5);
        int lane = threadIdx.x & 31;
        int h = warp >> 11;
        int t = warp & (TT - 1);

        const float4* kp = (const float4*)(k + ((size_t)(h * TT + t)) * DD);
        float4 a = kp[lane];
        float ks = a.x * a.x + a.y * a.y + a.z * a.z + a.w * a.w;

        const float4* vp = (const float4*)(v + ((size_t)(h * TT + t)) * DD);
        float4 bb = vp[lane];
        float vs = bb.x * bb.x + bb.y * bb.y + bb.z * bb.z + bb.w * bb.w;

        float4 acc = make_float4(0.f, 0.f, 0.f, 0.f);
#pragma unroll
        for (int g = 0; g < 4; ++g) {
            const float4* qp = (const float4*)(q + ((size_t)((h * 4 + g) * TT + t)) * DD);
            float4 u = __ldcs(&qp[lane]);
            acc.x += u.x; acc.y += u.y; acc.z += u.z; acc.w += u.w;
        }
        acc.x *= 0.25f; acc.y *= 0.25f; acc.z *= 0.25f; acc.w *= 0.25f;
        float qs = acc.x * acc.x + acc.y * acc.y + acc.z * acc.z + acc.w * acc.w;

#pragma unroll
        for (int o = 16; o > 0; o >>= 1) {
            ks += __shfl_xor_sync(0xffffffffu, ks, o);
            vs += __shfl_xor_sync(0xffffffffu, vs, o);
            qs += __shfl_xor_sync(0xffffffffu, qs, o);
        }
        if (lane == 0) {
            g_knorm[warp] = sqrtf(ks);
            g_vnorm[warp] = sqrtf(vs);
            g_qnorm[warp] = sqrtf(qs);
        }
    }
}

// ---------------- 2) wide priority: partial reduce + MLP, one thread per (h,t) ----------------
// 128 blocks x 128 threads; 16 blocks per head so weights are uniform per block.
__global__ void prio_kernel(const float* __restrict__ W1, const float* __restrict__ b1,
                            const float* __restrict__ W2, const float* __restrict__ b2) {
    int idx = blockIdx.x * 128 + threadIdx.x;  // 0..16383
    int h = idx >> 11;
    int t = idx & (TT - 1);

    __shared__ float sW1[50], sb1[10], sW2[10], sb2;
    if (threadIdx.x < 50) sW1[threadIdx.x] = W1[h * 50 + threadIdx.x];
    if (threadIdx.x >= 64 && threadIdx.x < 74) {
        sb1[threadIdx.x - 64] = b1[h * 10 + threadIdx.x - 64];
        sW2[threadIdx.x - 64] = W2[h * 10 + threadIdx.x - 64];
    }
    if (threadIdx.x == 96) sb2 = b2[h];
    __syncthreads();

    float s = 0.0f;
#pragma unroll
    for (int rc = 0; rc < RC; ++rc) s += g_part[(h * RC + rc) * TT + t];
    float f0 = s / (float)(TT - t);
    float f1 = g_knorm[idx];
    float f2 = g_vnorm[idx];
    float f3 = g_qnorm[idx];
    float f4 = g_enorm[t];

    float p = sb2;
#pragma unroll
    for (int kk = 0; kk < 10; ++kk) {
        float hs = sb1[kk];
        hs += f0 * sW1[kk];
        hs += f1 * sW1[10 + kk];
        hs += f2 * sW1[20 + kk];
        hs += f3 * sW1[30 + kk];
        hs += f4 * sW1[40 + kk];
        p += fmaxf(hs, 0.0f) * sW2[kk];
    }
    unsigned u = __float_as_uint(p);
    u = (u & 0x80000000u) ? ~u : (u | 0x80000000u);  // monotone order map
    g_prio_u[idx] = u;
}

// ---------------- 3) radix-select top-512 per head ----------------
// One block per head, 1024 threads. Exact top-512 by value, ties -> lower
// index (matches lax.top_k), indices ascending via stable t-order compaction.
__global__ void __launch_bounds__(1024, 1)
topk_kernel(float* __restrict__ out_idx_as_float) {
    int h = blockIdx.x;
    int tid = threadIdx.x;
    int lane = tid & 31, wid = tid >> 5;

    __shared__ unsigned su[TT];
    __shared__ unsigned hist[256];
    __shared__ unsigned wsum[32];
    __shared__ unsigned s_prefix;
    __shared__ int      s_rem;

    if (tid == 0) { s_prefix = 0u; s_rem = LL; }
    su[tid] = g_prio_u[h * TT + tid];
    su[tid + 1024] = g_prio_u[h * TT + tid + 1024];
    __syncthreads();

    // ---- 4-pass radix select of the 512th largest value (exact bits) ----
    for (int pass = 0; pass < 4; ++pass) {
        int shift = 24 - 8 * pass;
        if (tid < 256) hist[tid] = 0u;
        __syncthreads();
        unsigned pref = s_prefix;
#pragma unroll
        for (int t = tid; t < TT; t += 1024) {
            unsigned u = su[t];
            bool cand = (pass == 0) || ((u >> (shift + 8)) == (pref >> (shift + 8)));
            if (cand) atomicAdd(&hist[(u >> shift) & 255u], 1u);
        }
        __syncthreads();
        if (tid < 32) {
            int rem = s_rem;
            unsigned pfx = s_prefix;
            __syncwarp();
            unsigned local[8];
            unsigned lsum = 0;
#pragma unroll
            for (int i = 0; i < 8; ++i) { local[i] = hist[255 - (tid * 8 + i)]; lsum += local[i]; }
            unsigned inc = lsum;
#pragma unroll
            for (int o = 1; o < 32; o <<= 1) {
                unsigned n = __shfl_up_sync(0xffffffffu, inc, o);
                if (lane >= o) inc += n;
            }
            unsigned cum = inc - lsum;   // count in bins strictly above my group
#pragma unroll
            for (int i = 0; i < 8; ++i) {
                unsigned above = cum;
                cum += local[i];
                int bin = 255 - (tid * 8 + i);
                if (above < (unsigned)rem && cum >= (unsigned)rem) {
                    s_prefix = pfx | ((unsigned)bin << shift);
                    s_rem = rem - (int)above;
                }
            }
        }
        __syncthreads();
    }

    unsigned thr = s_prefix;           // exact bits of the 512th largest
    unsigned extra = (unsigned)s_rem;  // # of (== thr) elements to keep (lowest t first)

    // ---- stable compaction: selected = (u > thr) || (u == thr && eq_rank < extra)
    int t0 = 2 * tid, t1 = 2 * tid + 1;
    unsigned u0 = su[t0], u1 = su[t1];
    unsigned gt0 = (u0 > thr), eq0 = (u0 == thr);
    unsigned gt1 = (u1 > thr), eq1 = (u1 == thr);
    unsigned cnt = (gt0 + gt1) | ((eq0 + eq1) << 16);

    unsigned inc = cnt;
#pragma unroll
    for (int o = 1; o < 32; o <<= 1) {
        unsigned n = __shfl_up_sync(0xffffffffu, inc, o);
        if (lane >= o) inc += n;
    }
    if (lane == 31) wsum[wid] = inc;
    __syncthreads();
    if (tid < 32) {
        unsigned a = wsum[tid];
        unsigned in2 = a;
#pragma unroll
        for (int o = 1; o < 32; o <<= 1) {
            unsigned n = __shfl_up_sync(0xffffffffu, in2, o);
            if (lane >= o) in2 += n;
        }
        wsum[tid] = in2 - a;   // exclusive warp offsets
    }
    __syncthreads();
    unsigned excl = wsum[wid] + inc - cnt;     // packed exclusive prefix
    unsigned gt_b = excl & 0xffffu;
    unsigned eq_b = excl >> 16;

    if (gt0 || (eq0 && eq_b < extra)) {
        unsigned pos = gt_b + min(eq_b, extra);
        g_keep[h * LL + pos] = t0;
        out_idx_as_float[h * LL + pos] = (float)t0;
    }
    gt_b += gt0; eq_b += eq0;
    if (gt1 || (eq1 && eq_b < extra)) {
        unsigned pos = gt_b + min(eq_b, extra);
        g_keep[h * LL + pos] = t1;
        out_idx_as_float[h * LL + pos] = (float)t1;
    }
}

// ---------------- 4) gather: one warp per 2 rows, k+v both -> MLP=4 (best measured) ----------------
// 256 blocks x 256 threads = 2048 warps for 4096 rows.
__global__ void gather_kernel(const float* __restrict__ k,
                              const float* __restrict__ v,
                              float* __restrict__ out) {
    int widg = (blockIdx.x * blockDim.x + threadIdx.x) >> 5;  // 0..2047
    int lane = threadIdx.x & 31;
    int r0 = widg * 2;                 // rows r0, r0+1 (global row = h*512 + l)
    int h0 = r0 >> 9;
    int h1 = (r0 + 1) >> 9;

    // broadcast index loads (independent -> both in flight)
    int t0 = g_keep[r0];
    int t1 = g_keep[r0 + 1];

    // 4 independent 512B row reads in flight per warp (L2-hot after main)
    float4 k0 = ((const float4*)(k + ((size_t)(h0 * TT + t0)) * DD))[lane];
    float4 v0 = ((const float4*)(v + ((size_t)(h0 * TT + t0)) * DD))[lane];
    float4 k1 = ((const float4*)(k + ((size_t)(h1 * TT + t1)) * DD))[lane];
    float4 v1 = ((const float4*)(v + ((size_t)(h1 * TT + t1)) * DD))[lane];

    float* ko = out + (size_t)HH * LL;
    float* vo = ko + (size_t)HH * LL * DD;
    ((float4*)(ko + (size_t)r0 * DD))[lane] = k0;
    ((float4*)(vo + (size_t)r0 * DD))[lane] = v0;
    ((float4*)(ko + (size_t)(r0 + 1) * DD))[lane] = k1;
    ((float4*)(vo + (size_t)(r0 + 1) * DD))[lane] = v1;
}

// ---------------- launch ----------------
extern "C" void kernel_launch(void* const* d_in, const int* in_sizes, int n_in,
                              void* d_out, int out_size) {
    // metadata order: input_pos, k_val, v_val, query, x, attn, W1, b1, W2, b2
    const float* k    = (const float*)d_in[1];
    const float* v    = (const float*)d_in[2];
    const float* q    = (const float*)d_in[3];
    const float* x    = (const float*)d_in[4];
    const float* attn = (const float*)d_in[5];
    const float* W1   = (const float*)d_in[6];
    const float* b1   = (const float*)d_in[7];
    const float* W2   = (const float*)d_in[8];
    const float* b2   = (const float*)d_in[9];
    float* out = (float*)d_out;  // [keep_idxs(4096) | k_out(524288) | v_out(524288)]

    main_fused_kernel<<<NB_MAIN, 256>>>(attn, k, v, q, x);
    prio_kernel<<<HH * TT / 128, 128>>>(W1, b1, W2, b2);
    topk_kernel<<<HH, 1024>>>(out);
    gather_kernel<<<HH * LL / 16, 256>>>(k, v, out);
}